// round 1
// baseline (speedup 1.0000x reference)
#include <cuda_runtime.h>
#include <cstdint>
#include <cstddef>

// ---------------------------------------------------------------------------
// Scratch: x_proj buffer [B*T, H] = [262144, 256] fp32 = 256 MiB (static ok)
// ---------------------------------------------------------------------------
__device__ float g_xproj[64u * 4096u * 256u];

// ---------------------------------------------------------------------------
// Accurate tanh independent of --use_fast_math (EX2-based, ~1e-6 rel err)
// ---------------------------------------------------------------------------
__device__ __forceinline__ float my_tanh(float x) {
    float ax = fabsf(x);
    // 2*log2(e)
    float e = exp2f(ax * 2.88539008177793f);
    float t = 1.0f - 2.0f / (e + 1.0f);
    if (ax > 15.0f) t = 1.0f;
    return copysignf(t, x);
}

// ---------------------------------------------------------------------------
// Kernel 1: x_proj = x @ W_in^T + b_in
//   x: [M, K] (M = B*T, K = I), W_in: [N, K] (N = H), out: [M, N]
//   64x64 tile, BK=16, 256 threads, 4x4 micro-tile per thread.
// ---------------------------------------------------------------------------
#define XP_TILE 64
#define XP_BK   16

__global__ __launch_bounds__(256) void xproj_kernel(
    const float* __restrict__ x, const float* __restrict__ Win,
    const float* __restrict__ bin, float* __restrict__ out,
    int M, int K, int N)
{
    __shared__ float As[XP_BK][XP_TILE];
    __shared__ float Bs[XP_BK][XP_TILE];

    const int tid = threadIdx.x;
    const int tx = tid & 15;        // 0..15  -> N direction
    const int ty = tid >> 4;        // 0..15  -> M direction
    const int n0 = blockIdx.x * XP_TILE;
    const int m0 = blockIdx.y * XP_TILE;

    // loader mapping: 256 threads load 64 rows x 16 k (float4 each)
    const int lr = tid >> 2;          // 0..63 row
    const int lc = (tid & 3) * 4;     // 0,4,8,12 k-offset

    float c[4][4];
    #pragma unroll
    for (int i = 0; i < 4; i++)
        #pragma unroll
        for (int jj = 0; jj < 4; jj++) c[i][jj] = 0.0f;

    for (int k0 = 0; k0 < K; k0 += XP_BK) {
        float4 xa = *(const float4*)(x   + (size_t)(m0 + lr) * K + k0 + lc);
        float4 wb = *(const float4*)(Win + (size_t)(n0 + lr) * K + k0 + lc);
        As[lc + 0][lr] = xa.x; As[lc + 1][lr] = xa.y;
        As[lc + 2][lr] = xa.z; As[lc + 3][lr] = xa.w;
        Bs[lc + 0][lr] = wb.x; Bs[lc + 1][lr] = wb.y;
        Bs[lc + 2][lr] = wb.z; Bs[lc + 3][lr] = wb.w;
        __syncthreads();

        #pragma unroll
        for (int kk = 0; kk < XP_BK; kk++) {
            float4 a = *(const float4*)(&As[kk][ty * 4]);
            float4 b = *(const float4*)(&Bs[kk][tx * 4]);
            float av[4] = {a.x, a.y, a.z, a.w};
            float bv[4] = {b.x, b.y, b.z, b.w};
            #pragma unroll
            for (int mi = 0; mi < 4; mi++)
                #pragma unroll
                for (int ni = 0; ni < 4; ni++)
                    c[mi][ni] = fmaf(av[mi], bv[ni], c[mi][ni]);
        }
        __syncthreads();
    }

    #pragma unroll
    for (int mi = 0; mi < 4; mi++) {
        int row = m0 + ty * 4 + mi;
        #pragma unroll
        for (int ni = 0; ni < 4; ni++) {
            int col = n0 + tx * 4 + ni;
            out[(size_t)row * N + col] = c[mi][ni] + __ldg(&bin[col]);
        }
    }
}

// ---------------------------------------------------------------------------
// Kernel 2: persistent LTC scan. One CTA per batch element (H = 256 fixed).
//   W_rec split: columns i in [0,192) in smem (float4-transposed, 192 KB),
//                columns i in [192,256) in registers (16 float4 per thread).
//   h double-buffered in smem -> one __syncthreads per inner iteration.
// ---------------------------------------------------------------------------
#define LTC_H 256
#define NSM4  48   // 48 float4-groups (192 columns) from smem
#define NRG4  16   // 16 float4-groups (64 columns) from registers

__global__ __launch_bounds__(256, 1) void ltc_scan_kernel(
    const float* __restrict__ xproj,
    const float* __restrict__ Wrec,
    const float* __restrict__ brec,
    const float* __restrict__ tau,
    const int*   __restrict__ nl_p,
    float* __restrict__ out, int T)
{
    extern __shared__ float smem[];
    float4* ws4  = (float4*)smem;                         // NSM4*256 float4 = 192 KB
    float*  hbuf = smem + (size_t)NSM4 * LTC_H * 4;       // 2 * 256 floats

    const int b = blockIdx.x;
    const int j = threadIdx.x;   // output index 0..255

    // --- Load weights: thread j owns row j of W_rec -----------------------
    // smem layout: ws4[i4*256 + j] = { W[j][4*i4 .. 4*i4+3] }  (i4 < 48)
    #pragma unroll
    for (int i4 = 0; i4 < NSM4; i4++)
        ws4[i4 * LTC_H + j] = *(const float4*)(Wrec + (size_t)j * LTC_H + i4 * 4);

    float4 wr[NRG4];
    #pragma unroll
    for (int k = 0; k < NRG4; k++)
        wr[k] = *(const float4*)(Wrec + (size_t)j * LTC_H + NSM4 * 4 + k * 4);

    const float brec_j = brec[j];
    float tauc = tau[j];
    tauc = fminf(fmaxf(tauc, 0.1f), 5.0f);
    const float scale_j = 0.1f / tauc;

    int NL = 2;
    if (nl_p) {
        int v = *nl_p;
        if (v >= 1 && v <= 64) NL = v;   // guard against non-int encodings
    }

    hbuf[j] = 0.0f;
    hbuf[LTC_H + j] = 0.0f;
    float hj = 0.0f;
    __syncthreads();

    const float* xrow = xproj + ((size_t)b * T) * LTC_H + j;
    float xt = __ldg(xrow);     // prefetch t = 0
    int cur = 0;

    for (int t = 0; t < T; t++) {
        const float xf = xt;
        if (t + 1 < T) xt = __ldg(xrow + (size_t)(t + 1) * LTC_H);  // prefetch next
        const float base = xf + brec_j;

        for (int l = 0; l < NL; l++) {
            const float4* hp = (const float4*)(hbuf + cur * LTC_H);
            float a0 = base, a1 = 0.0f, a2 = 0.0f, a3 = 0.0f;

            #pragma unroll
            for (int i4 = 0; i4 < NSM4; i4++) {
                float4 w  = ws4[i4 * LTC_H + j];   // conflict-free LDS.128
                float4 hv = hp[i4];                // broadcast LDS.128
                a0 = fmaf(w.x, hv.x, a0);
                a1 = fmaf(w.y, hv.y, a1);
                a2 = fmaf(w.z, hv.z, a2);
                a3 = fmaf(w.w, hv.w, a3);
            }
            #pragma unroll
            for (int k = 0; k < NRG4; k++) {
                float4 hv = hp[NSM4 + k];          // broadcast LDS.128
                a0 = fmaf(wr[k].x, hv.x, a0);
                a1 = fmaf(wr[k].y, hv.y, a1);
                a2 = fmaf(wr[k].z, hv.z, a2);
                a3 = fmaf(wr[k].w, hv.w, a3);
            }
            float acc = (a0 + a1) + (a2 + a3);
            float act = my_tanh(acc);
            hj = fmaf(scale_j, act - hj, hj);

            cur ^= 1;
            hbuf[cur * LTC_H + j] = hj;   // write to the *other* buffer
            __syncthreads();
        }
    }

    out[(size_t)b * LTC_H + j] = hj;
}

// ---------------------------------------------------------------------------
// Launcher
// inputs (metadata order): x, W_in, b_in, W_rec, b_rec, tau, num_layers
// ---------------------------------------------------------------------------
extern "C" void kernel_launch(void* const* d_in, const int* in_sizes, int n_in,
                              void* d_out, int out_size)
{
    const float* x    = (const float*)d_in[0];
    const float* Win  = (const float*)d_in[1];
    const float* bin  = (const float*)d_in[2];
    const float* Wrec = (const float*)d_in[3];
    const float* brec = (const float*)d_in[4];
    const float* tau  = (const float*)d_in[5];
    const int*   nl   = (n_in > 6) ? (const int*)d_in[6] : nullptr;

    const int H = in_sizes[2];              // 256
    const int I = in_sizes[1] / H;          // 128
    const int B = out_size / H;             // 64
    const int T = in_sizes[0] / (B * I);    // 4096
    const int M = B * T;                    // 262144

    float* xproj = nullptr;
    cudaGetSymbolAddress((void**)&xproj, g_xproj);

    // Kernel 1: input projection (parallel over all B*T rows)
    dim3 grid1(H / XP_TILE, M / XP_TILE);
    xproj_kernel<<<grid1, 256>>>(x, Win, bin, xproj, M, I, H);

    // Kernel 2: persistent scan, one CTA per batch element
    size_t smem_bytes = (size_t)NSM4 * LTC_H * sizeof(float4)
                      + 2 * LTC_H * sizeof(float);
    cudaFuncSetAttribute(ltc_scan_kernel,
                         cudaFuncAttributeMaxDynamicSharedMemorySize,
                         (int)smem_bytes);
    ltc_scan_kernel<<<B, LTC_H, smem_bytes>>>(xproj, Wrec, brec, tau, nl,
                                              (float*)d_out, T);
}

// round 2
// speedup vs baseline: 1.4278x; 1.4278x over previous
#include <cuda_runtime.h>
#include <cstdint>
#include <cstddef>

// ---------------------------------------------------------------------------
// Scratch: x_proj buffer [B*T, H] = [262144, 256] fp32 = 256 MiB
// ---------------------------------------------------------------------------
__device__ float g_xproj[64u * 4096u * 256u];

// ---------------------------------------------------------------------------
// Accurate tanh independent of --use_fast_math (EX2-based, ~1e-6 rel err)
// ---------------------------------------------------------------------------
__device__ __forceinline__ float my_tanh(float x) {
    float ax = fabsf(x);
    float e = exp2f(ax * 2.88539008177793f);   // 2*log2(e)
    float t = 1.0f - 2.0f / (e + 1.0f);
    if (ax > 15.0f) t = 1.0f;
    return copysignf(t, x);
}

// ---------------------------------------------------------------------------
// Packed f32x2 FMA (FFMA2): d = a*b + c elementwise on two packed fp32
// ---------------------------------------------------------------------------
__device__ __forceinline__ uint64_t ffma2(uint64_t a, uint64_t b, uint64_t c) {
    uint64_t d;
    asm("fma.rn.f32x2 %0, %1, %2, %3;" : "=l"(d) : "l"(a), "l"(b), "l"(c));
    return d;
}
__device__ __forceinline__ float f2lo_add(uint64_t v) {
    float lo, hi;
    asm("mov.b64 {%0, %1}, %2;" : "=f"(lo), "=f"(hi) : "l"(v));
    return lo + hi;
}

__device__ __forceinline__ uint32_t smem_u32(const void* p) {
    uint32_t a;
    asm("{ .reg .u64 t; cvta.to.shared.u64 t, %1; cvt.u32.u64 %0, t; }"
        : "=r"(a) : "l"(p));
    return a;
}

__device__ __forceinline__ void st_shared_remote(uint32_t laddr, uint32_t peer, float v) {
    uint32_t raddr;
    asm volatile("mapa.shared::cluster.u32 %0, %1, %2;" : "=r"(raddr) : "r"(laddr), "r"(peer));
    asm volatile("st.shared::cluster.f32 [%0], %1;" :: "r"(raddr), "f"(v) : "memory");
}

#define CLUSTER_ARRIVE() asm volatile("barrier.cluster.arrive.aligned;" ::: "memory")
#define CLUSTER_WAIT()   asm volatile("barrier.cluster.wait.aligned;" ::: "memory")

// ---------------------------------------------------------------------------
// Kernel 1: x_proj = x @ W_in^T + b_in   (unchanged from R1 — not the bottleneck)
// ---------------------------------------------------------------------------
#define XP_TILE 64
#define XP_BK   16

__global__ __launch_bounds__(256) void xproj_kernel(
    const float* __restrict__ x, const float* __restrict__ Win,
    const float* __restrict__ bin, float* __restrict__ out,
    int M, int K, int N)
{
    __shared__ float As[XP_BK][XP_TILE];
    __shared__ float Bs[XP_BK][XP_TILE];

    const int tid = threadIdx.x;
    const int tx = tid & 15;
    const int ty = tid >> 4;
    const int n0 = blockIdx.x * XP_TILE;
    const int m0 = blockIdx.y * XP_TILE;

    const int lr = tid >> 2;
    const int lc = (tid & 3) * 4;

    float c[4][4];
    #pragma unroll
    for (int i = 0; i < 4; i++)
        #pragma unroll
        for (int jj = 0; jj < 4; jj++) c[i][jj] = 0.0f;

    for (int k0 = 0; k0 < K; k0 += XP_BK) {
        float4 xa = *(const float4*)(x   + (size_t)(m0 + lr) * K + k0 + lc);
        float4 wb = *(const float4*)(Win + (size_t)(n0 + lr) * K + k0 + lc);
        As[lc + 0][lr] = xa.x; As[lc + 1][lr] = xa.y;
        As[lc + 2][lr] = xa.z; As[lc + 3][lr] = xa.w;
        Bs[lc + 0][lr] = wb.x; Bs[lc + 1][lr] = wb.y;
        Bs[lc + 2][lr] = wb.z; Bs[lc + 3][lr] = wb.w;
        __syncthreads();

        #pragma unroll
        for (int kk = 0; kk < XP_BK; kk++) {
            float4 a = *(const float4*)(&As[kk][ty * 4]);
            float4 b = *(const float4*)(&Bs[kk][tx * 4]);
            float av[4] = {a.x, a.y, a.z, a.w};
            float bv[4] = {b.x, b.y, b.z, b.w};
            #pragma unroll
            for (int mi = 0; mi < 4; mi++)
                #pragma unroll
                for (int ni = 0; ni < 4; ni++)
                    c[mi][ni] = fmaf(av[mi], bv[ni], c[mi][ni]);
        }
        __syncthreads();
    }

    #pragma unroll
    for (int mi = 0; mi < 4; mi++) {
        int row = m0 + ty * 4 + mi;
        #pragma unroll
        for (int ni = 0; ni < 4; ni++) {
            int col = n0 + tx * 4 + ni;
            out[(size_t)row * N + col] = c[mi][ni] + __ldg(&bin[col]);
        }
    }
}

// ---------------------------------------------------------------------------
// Kernel 2: persistent LTC scan, 2-CTA cluster per batch element.
//   CTA rank r owns outputs j in [r*128, r*128+128).
//   Thread t: j_local = t>>1, k-half = t&1 (cols kh*128 .. kh*128+127).
//   W_rec slice: 128 floats = 64 packed f32x2 REGISTERS per thread (no smem W).
//   h: full 256-vector double-buffered in each CTA's smem; after each inner
//   iter the owning lane-pair writes h_j locally (even lane) and to the peer
//   CTA via DSMEM (odd lane); cluster barrier separates write/read phases.
// ---------------------------------------------------------------------------
#define LTC_H 256

__global__ __launch_bounds__(256, 1) __cluster_dims__(2, 1, 1)
void ltc_scan_kernel(
    const float* __restrict__ xproj,
    const float* __restrict__ Wrec,
    const float* __restrict__ brec,
    const float* __restrict__ tau,
    const int*   __restrict__ nl_p,
    float* __restrict__ out, int T)
{
    __shared__ __align__(16) float hbuf[2][LTC_H];

    const int b = blockIdx.x >> 1;
    uint32_t rank;
    asm("mov.u32 %0, %%cluster_ctarank;" : "=r"(rank));
    const uint32_t peer = rank ^ 1u;

    const int t_  = threadIdx.x;
    const int jl  = t_ >> 1;           // local output 0..127
    const int kh  = t_ & 1;            // k-half
    const int j   = (int)rank * 128 + jl;   // global output index

    // --- W_rec[j][kh*128 .. +127] into 64 packed-f32x2 registers ----------
    uint64_t wd[64];
    {
        const ulonglong2* wrow =
            (const ulonglong2*)(Wrec + (size_t)j * LTC_H + (kh << 7));
        #pragma unroll
        for (int i = 0; i < 32; i++) {
            ulonglong2 v = wrow[i];
            wd[2 * i]     = v.x;
            wd[2 * i + 1] = v.y;
        }
    }

    const float brec_j = brec[j];
    float tauc = fminf(fmaxf(tau[j], 0.1f), 5.0f);
    const float scale_j = 0.1f / tauc;

    int NL = 2;
    if (nl_p) {
        int v = *nl_p;
        if (v >= 1 && v <= 64) NL = v;
    }

    // zero both h buffers
    hbuf[0][t_] = 0.0f;
    hbuf[1][t_] = 0.0f;
    float hj = 0.0f;
    __syncthreads();
    CLUSTER_ARRIVE();
    CLUSTER_WAIT();

    const float* xrow = xproj + ((size_t)b * T) * LTC_H + j;
    float xt = __ldg(xrow);            // prefetch t = 0
    int cur = 0;

    for (int t = 0; t < T; t++) {
        const float base = xt + brec_j;
        if (t + 1 < T) xt = __ldg(xrow + (size_t)(t + 1) * LTC_H);

        for (int l = 0; l < NL; l++) {
            const ulonglong2* hp =
                (const ulonglong2*)(hbuf[cur] + (kh << 7));
            uint64_t a0 = 0ull, a1 = 0ull, a2 = 0ull, a3 = 0ull;

            #pragma unroll
            for (int i = 0; i < 32; i += 2) {
                ulonglong2 h0 = hp[i];
                ulonglong2 h1 = hp[i + 1];
                a0 = ffma2(wd[2 * i],     h0.x, a0);
                a1 = ffma2(wd[2 * i + 1], h0.y, a1);
                a2 = ffma2(wd[2 * i + 2], h1.x, a2);
                a3 = ffma2(wd[2 * i + 3], h1.y, a3);
            }
            float sum = (f2lo_add(a0) + f2lo_add(a1))
                      + (f2lo_add(a2) + f2lo_add(a3));
            // pair reduction: lanes (2m, 2m+1) hold the two K-halves
            sum += __shfl_xor_sync(0xffffffffu, sum, 1);

            float act = my_tanh(base + sum);
            hj = fmaf(scale_j, act - hj, hj);

            const int nxt = cur ^ 1;
            if (kh == 0) {
                hbuf[nxt][j] = hj;                         // local copy
            } else {
                st_shared_remote(smem_u32(&hbuf[nxt][j]), peer, hj);  // peer copy
            }
            CLUSTER_ARRIVE();   // release: orders local + remote h stores
            CLUSTER_WAIT();     // acquire: peer's h stores visible after this
            cur = nxt;
        }
    }

    if (kh == 0) out[(size_t)b * LTC_H + j] = hj;
}

// ---------------------------------------------------------------------------
// Launcher — inputs: x, W_in, b_in, W_rec, b_rec, tau, num_layers
// ---------------------------------------------------------------------------
extern "C" void kernel_launch(void* const* d_in, const int* in_sizes, int n_in,
                              void* d_out, int out_size)
{
    const float* x    = (const float*)d_in[0];
    const float* Win  = (const float*)d_in[1];
    const float* bin  = (const float*)d_in[2];
    const float* Wrec = (const float*)d_in[3];
    const float* brec = (const float*)d_in[4];
    const float* tau  = (const float*)d_in[5];
    const int*   nl   = (n_in > 6) ? (const int*)d_in[6] : nullptr;

    const int H = in_sizes[2];              // 256
    const int I = in_sizes[1] / H;          // 128
    const int B = out_size / H;             // 64
    const int T = in_sizes[0] / (B * I);    // 4096
    const int M = B * T;

    float* xproj = nullptr;
    cudaGetSymbolAddress((void**)&xproj, g_xproj);

    dim3 grid1(H / XP_TILE, M / XP_TILE);
    xproj_kernel<<<grid1, 256>>>(x, Win, bin, xproj, M, I, H);

    // 2 CTAs per batch element (cluster), 256 threads each
    ltc_scan_kernel<<<2 * B, LTC_H>>>(xproj, Wrec, brec, tau, nl,
                                      (float*)d_out, T);
}

// round 3
// speedup vs baseline: 2.5146x; 1.7612x over previous
#include <cuda_runtime.h>
#include <cstdint>
#include <cstddef>

// ---------------------------------------------------------------------------
// Scratch: x_proj buffer [B*T, H] = [262144, 256] fp32 = 256 MiB
// ---------------------------------------------------------------------------
__device__ float g_xproj[64u * 4096u * 256u];

// ---------------------------------------------------------------------------
// Accurate tanh independent of --use_fast_math (EX2-based, ~1e-6 rel err)
// ---------------------------------------------------------------------------
__device__ __forceinline__ float my_tanh(float x) {
    float ax = fabsf(x);
    float e = exp2f(ax * 2.88539008177793f);   // 2*log2(e)
    float t = 1.0f - 2.0f / (e + 1.0f);
    if (ax > 15.0f) t = 1.0f;
    return copysignf(t, x);
}

// ---------------------------------------------------------------------------
// Packed f32x2 helpers
// ---------------------------------------------------------------------------
__device__ __forceinline__ uint64_t ffma2(uint64_t a, uint64_t b, uint64_t c) {
    uint64_t d;
    asm("fma.rn.f32x2 %0, %1, %2, %3;" : "=l"(d) : "l"(a), "l"(b), "l"(c));
    return d;
}
__device__ __forceinline__ float f2sum(uint64_t v) {
    float lo, hi;
    asm("mov.b64 {%0, %1}, %2;" : "=f"(lo), "=f"(hi) : "l"(v));
    return lo + hi;
}

__device__ __forceinline__ uint32_t smem_u32(const void* p) {
    uint32_t a;
    asm("{ .reg .u64 t; cvta.to.shared.u64 t, %1; cvt.u32.u64 %0, t; }"
        : "=r"(a) : "l"(p));
    return a;
}
__device__ __forceinline__ uint32_t mapa_peer(uint32_t laddr, uint32_t peer) {
    uint32_t raddr;
    asm("mapa.shared::cluster.u32 %0, %1, %2;" : "=r"(raddr) : "r"(laddr), "r"(peer));
    return raddr;
}
// Remote store of 4 bytes that completes tx on the peer's mbarrier.
__device__ __forceinline__ void st_async_remote(uint32_t raddr, float v, uint32_t rmbar) {
    asm volatile(
        "st.async.shared::cluster.mbarrier::complete_tx::bytes.b32 [%0], %1, [%2];"
        :: "r"(raddr), "r"(__float_as_uint(v)), "r"(rmbar) : "memory");
}
__device__ __forceinline__ void mbar_init(uint32_t addr, uint32_t cnt) {
    asm volatile("mbarrier.init.shared.b64 [%0], %1;" :: "r"(addr), "r"(cnt) : "memory");
}
__device__ __forceinline__ void mbar_arrive_expect_tx(uint32_t addr, uint32_t tx) {
    asm volatile("mbarrier.arrive.expect_tx.shared.b64 _, [%0], %1;"
                 :: "r"(addr), "r"(tx) : "memory");
}
__device__ __forceinline__ void mbar_wait_parity(uint32_t addr, uint32_t parity) {
    uint32_t done;
    asm volatile(
        "{\n\t.reg .pred p;\n\t"
        "mbarrier.try_wait.parity.acquire.cta.shared::cta.b64 p, [%1], %2;\n\t"
        "selp.b32 %0, 1, 0, p;\n\t}"
        : "=r"(done) : "r"(addr), "r"(parity) : "memory");
    if (!done) {
        asm volatile(
            "{\n\t.reg .pred P1;\n\t"
            "WL_%=:\n\t"
            "mbarrier.try_wait.parity.acquire.cta.shared::cta.b64 P1, [%0], %1, 0x989680;\n\t"
            "@P1 bra.uni WD_%=;\n\t"
            "bra.uni WL_%=;\n\t"
            "WD_%=:\n\t}"
            :: "r"(addr), "r"(parity) : "memory");
    }
}

#define CLUSTER_SYNC_() do { \
    asm volatile("barrier.cluster.arrive.aligned;" ::: "memory"); \
    asm volatile("barrier.cluster.wait.aligned;" ::: "memory"); } while (0)

// ---------------------------------------------------------------------------
// Kernel 1: x_proj = x @ W_in^T + b_in
//   128x128 tile, BK=16, 256 threads, 8x8 micro-tile.
// ---------------------------------------------------------------------------
#define XP_BM 128
#define XP_BN 128
#define XP_BK 16

__global__ __launch_bounds__(256) void xproj_kernel(
    const float* __restrict__ x, const float* __restrict__ Win,
    const float* __restrict__ bin, float* __restrict__ out,
    int M, int K, int N)
{
    __shared__ float As[XP_BK][XP_BM];
    __shared__ float Bs[XP_BK][XP_BN];

    const int tid = threadIdx.x;
    const int tx = tid & 15;          // N direction (8 cols each)
    const int ty = tid >> 4;          // M direction (8 rows each)
    const int n0 = blockIdx.x * XP_BN;
    const int m0 = blockIdx.y * XP_BM;

    // loader: 256 threads; each loads 2 float4 from A and 2 from B per k-block
    const int lr = tid >> 1;          // 0..127 row
    const int lc = (tid & 1) * 8;     // 0 or 8 k-offset

    float c[8][8];
    #pragma unroll
    for (int i = 0; i < 8; i++)
        #pragma unroll
        for (int jj = 0; jj < 8; jj++) c[i][jj] = 0.0f;

    for (int k0 = 0; k0 < K; k0 += XP_BK) {
        float4 xa0 = *(const float4*)(x   + (size_t)(m0 + lr) * K + k0 + lc);
        float4 xa1 = *(const float4*)(x   + (size_t)(m0 + lr) * K + k0 + lc + 4);
        float4 wb0 = *(const float4*)(Win + (size_t)(n0 + lr) * K + k0 + lc);
        float4 wb1 = *(const float4*)(Win + (size_t)(n0 + lr) * K + k0 + lc + 4);
        As[lc + 0][lr] = xa0.x; As[lc + 1][lr] = xa0.y;
        As[lc + 2][lr] = xa0.z; As[lc + 3][lr] = xa0.w;
        As[lc + 4][lr] = xa1.x; As[lc + 5][lr] = xa1.y;
        As[lc + 6][lr] = xa1.z; As[lc + 7][lr] = xa1.w;
        Bs[lc + 0][lr] = wb0.x; Bs[lc + 1][lr] = wb0.y;
        Bs[lc + 2][lr] = wb0.z; Bs[lc + 3][lr] = wb0.w;
        Bs[lc + 4][lr] = wb1.x; Bs[lc + 5][lr] = wb1.y;
        Bs[lc + 6][lr] = wb1.z; Bs[lc + 7][lr] = wb1.w;
        __syncthreads();

        #pragma unroll
        for (int kk = 0; kk < XP_BK; kk++) {
            float4 a0 = *(const float4*)(&As[kk][ty * 8]);
            float4 a1 = *(const float4*)(&As[kk][ty * 8 + 4]);
            float4 b0 = *(const float4*)(&Bs[kk][tx * 8]);
            float4 b1 = *(const float4*)(&Bs[kk][tx * 8 + 4]);
            float av[8] = {a0.x, a0.y, a0.z, a0.w, a1.x, a1.y, a1.z, a1.w};
            float bv[8] = {b0.x, b0.y, b0.z, b0.w, b1.x, b1.y, b1.z, b1.w};
            #pragma unroll
            for (int mi = 0; mi < 8; mi++)
                #pragma unroll
                for (int ni = 0; ni < 8; ni++)
                    c[mi][ni] = fmaf(av[mi], bv[ni], c[mi][ni]);
        }
        __syncthreads();
    }

    float bb[8];
    #pragma unroll
    for (int ni = 0; ni < 8; ni++) bb[ni] = __ldg(&bin[n0 + tx * 8 + ni]);

    #pragma unroll
    for (int mi = 0; mi < 8; mi++) {
        int row = m0 + ty * 8 + mi;
        float4 o0 = make_float4(c[mi][0] + bb[0], c[mi][1] + bb[1],
                                c[mi][2] + bb[2], c[mi][3] + bb[3]);
        float4 o1 = make_float4(c[mi][4] + bb[4], c[mi][5] + bb[5],
                                c[mi][6] + bb[6], c[mi][7] + bb[7]);
        *(float4*)(out + (size_t)row * N + n0 + tx * 8)     = o0;
        *(float4*)(out + (size_t)row * N + n0 + tx * 8 + 4) = o1;
    }
}

// ---------------------------------------------------------------------------
// Kernel 2: LTC scan, 2-CTA cluster per batch element, K-SPLIT.
//   CTA rank r: thread t owns output t and K-columns [r*128, r*128+128)
//   (128 fp32 = 64 packed f32x2 registers). Each CTA computes 256 partials,
//   pushes them to the peer via st.async (tx mbarrier), then both CTAs
//   redundantly finish tanh + h update -> h is fully CTA-local.
//   Per inner iter: 1 mbar try_wait + 1 bar.sync. No cluster barrier in loop.
// ---------------------------------------------------------------------------
#define LTC_H 256

__global__ __launch_bounds__(256, 1) __cluster_dims__(2, 1, 1)
void ltc_scan_kernel(
    const float* __restrict__ xproj,
    const float* __restrict__ Wrec,
    const float* __restrict__ brec,
    const float* __restrict__ tau,
    const int*   __restrict__ nl_p,
    float* __restrict__ out, int T)
{
    __shared__ __align__(16) float hbuf[2][LTC_H];    // double-buffered h
    __shared__ __align__(16) float ppart[2][LTC_H];   // peer partials, per slot
    __shared__ __align__(16) unsigned long long mbar[2];

    const int b = blockIdx.x >> 1;
    uint32_t rank;
    asm("mov.u32 %0, %%cluster_ctarank;" : "=r"(rank));
    const uint32_t peer = rank ^ 1u;

    const int t_ = threadIdx.x;   // output index 0..255

    // --- W_rec[t][rank*128 .. +127] -> 64 packed f32x2 registers ----------
    uint64_t wd[64];
    {
        const ulonglong2* wrow =
            (const ulonglong2*)(Wrec + (size_t)t_ * LTC_H + (rank << 7));
        #pragma unroll
        for (int i = 0; i < 32; i++) {
            ulonglong2 v = wrow[i];
            wd[2 * i]     = v.x;
            wd[2 * i + 1] = v.y;
        }
    }

    const float brec_j = brec[t_];
    const float scale_j = 0.1f / fminf(fmaxf(tau[t_], 0.1f), 5.0f);

    int NL = 2;
    if (nl_p) {
        int v = *nl_p;
        if (v >= 1 && v <= 64) NL = v;
    }

    // mbarriers + smem init
    const uint32_t mb0 = smem_u32(&mbar[0]);
    const uint32_t mb1 = smem_u32(&mbar[1]);
    if (t_ == 0) { mbar_init(mb0, 1); mbar_init(mb1, 1); }
    hbuf[0][t_] = 0.0f;
    hbuf[1][t_] = 0.0f;
    __syncthreads();
    CLUSTER_SYNC_();   // peer mbarriers visible before any st.async

    // remote addresses (peer's ppart slot entries and peer's mbars)
    const uint32_t r_pp0  = mapa_peer(smem_u32(&ppart[0][t_]), peer);
    const uint32_t r_pp1  = mapa_peer(smem_u32(&ppart[1][t_]), peer);
    const uint32_t r_mb0  = mapa_peer(mb0, peer);
    const uint32_t r_mb1  = mapa_peer(mb1, peer);

    const float* xrow = xproj + ((size_t)b * T) * LTC_H + t_;
    float xt = __ldg(xrow);            // prefetch t = 0
    float hj = 0.0f;
    int cur = 0;
    unsigned it = 0;                   // global inner-iteration counter

    for (int t = 0; t < T; t++) {
        const float base = xt + brec_j;
        if (t + 1 < T) xt = __ldg(xrow + (size_t)(t + 1) * LTC_H);

        for (int l = 0; l < NL; l++) {
            const int      slot   = it & 1u;
            const uint32_t parity = (it >> 1) & 1u;
            const uint32_t mloc   = slot ? mb1 : mb0;
            const uint32_t mrem   = slot ? r_mb1 : r_mb0;
            const uint32_t prem   = slot ? r_pp1 : r_pp0;

            // Arm this phase: 1 arrive + expect 256*4 bytes from the peer.
            // (arrive.expect_tx makes tx-before-arm ordering race-free.)
            if (t_ == 0) mbar_arrive_expect_tx(mloc, LTC_H * 4u);

            // ---- partial dot product over my K-half ----
            const ulonglong2* hp = (const ulonglong2*)(hbuf[cur] + (rank << 7));
            uint64_t a0 = 0ull, a1 = 0ull, a2 = 0ull, a3 = 0ull;
            #pragma unroll
            for (int i = 0; i < 32; i += 2) {
                ulonglong2 h0 = hp[i];
                ulonglong2 h1 = hp[i + 1];
                a0 = ffma2(wd[2 * i],     h0.x, a0);
                a1 = ffma2(wd[2 * i + 1], h0.y, a1);
                a2 = ffma2(wd[2 * i + 2], h1.x, a2);
                a3 = ffma2(wd[2 * i + 3], h1.y, a3);
            }
            const float part = (f2sum(a0) + f2sum(a1)) + (f2sum(a2) + f2sum(a3));

            // ---- push my partial to the peer (completes peer's mbar tx) ----
            st_async_remote(prem, part, mrem);

            // ---- wait for the peer's 256 partials ----
            mbar_wait_parity(mloc, parity);

            // ---- finish output t redundantly (identical fp on both CTAs) ----
            const float sum = part + ppart[slot][t_];
            const float act = my_tanh(base + sum);
            hj = fmaf(scale_j, act - hj, hj);

            const int nxt = cur ^ 1;
            hbuf[nxt][t_] = hj;
            __syncthreads();           // local h visible for next iteration
            cur = nxt;
            it++;
        }
    }

    if (rank == 0) out[(size_t)b * LTC_H + t_] = hj;

    CLUSTER_SYNC_();   // don't exit while peer st.async may target our smem
}

// ---------------------------------------------------------------------------
// Launcher — inputs: x, W_in, b_in, W_rec, b_rec, tau, num_layers
// ---------------------------------------------------------------------------
extern "C" void kernel_launch(void* const* d_in, const int* in_sizes, int n_in,
                              void* d_out, int out_size)
{
    const float* x    = (const float*)d_in[0];
    const float* Win  = (const float*)d_in[1];
    const float* bin  = (const float*)d_in[2];
    const float* Wrec = (const float*)d_in[3];
    const float* brec = (const float*)d_in[4];
    const float* tau  = (const float*)d_in[5];
    const int*   nl   = (n_in > 6) ? (const int*)d_in[6] : nullptr;

    const int H = in_sizes[2];              // 256
    const int I = in_sizes[1] / H;          // 128
    const int B = out_size / H;             // 64
    const int T = in_sizes[0] / (B * I);    // 4096
    const int M = B * T;

    float* xproj = nullptr;
    cudaGetSymbolAddress((void**)&xproj, g_xproj);

    dim3 grid1(H / XP_BN, M / XP_BM);
    xproj_kernel<<<grid1, 256>>>(x, Win, bin, xproj, M, I, H);

    ltc_scan_kernel<<<2 * B, LTC_H>>>(xproj, Wrec, brec, tau, nl,
                                      (float*)d_out, T);
}